// round 12
// baseline (speedup 1.0000x reference)
#include <cuda_runtime.h>
#include <cstdint>
#include <math.h>

// Problem dims
#define Bn   64
#define Tn   1024
#define TWOK 512
#define En   128
#define Hh   256
#define FH   1024          // 4*H
#define BT   (Bn*Tn)       // 65536
#define KXC  264           // 2E+1 padded to multiple of 8
#define HROW 288           // skewed h row stride (8 chunks of 36 floats)
#define PROBE_T 32
#define SENT 0xFFC00000u   // negative quiet NaN sentinel (probe only)

// ---------------- packed fp32x2 helpers ----------------
__device__ __forceinline__ void fma2(unsigned long long& acc,
                                     unsigned long long a,
                                     unsigned long long b) {
    asm("fma.rn.f32x2 %0, %1, %2, %0;" : "+l"(acc) : "l"(a), "l"(b));
}
__device__ __forceinline__ float2 unpk(unsigned long long v) {
    float2 r;
    asm("mov.b64 {%0, %1}, %2;" : "=f"(r.x), "=f"(r.y) : "l"(v));
    return r;
}
__device__ __forceinline__ float sigf(float x) {
    return fmaf(__tanhf(0.5f * x), 0.5f, 0.5f);
}
__device__ __forceinline__ float4 ldcg4v(const float4* p) {
    float4 v;
    asm volatile("ld.global.cg.v4.f32 {%0,%1,%2,%3}, [%4];"
                 : "=f"(v.x), "=f"(v.y), "=f"(v.z), "=f"(v.w)
                 : "l"(p) : "memory");
    return v;
}

// ---------------- scratch (static device globals) ----------------
__device__ float g_s[BT];
__device__ float g_Pt[BT];
__device__ float g_Cin[Bn * 8 * TWOK];
__device__ float g_cl[(size_t)BT * TWOK];
__device__ float g_xc[(size_t)BT * KXC];
__device__ float g_WlP[KXC * FH];
__device__ float g_blP[FH];
__device__ float g_pre[(size_t)BT * FH];           // [t*64+b][FH] permuted cols
__device__ float g_H[(size_t)BT * Hh];             // [t][b][256] time-major
__device__ float g_Hp[(size_t)PROBE_T * Bn * Hh];  // probe h buffer
__device__ float g_Y[(size_t)BT * Hh];             // rows in t*64+b order
__device__ int   g_rbar[8 * 32];                   // row barriers (128B apart)

// ---------------- tiny kernels ----------------
__global__ void k_reset() {
    int i = threadIdx.x;
    if (i < 8 * 32) g_rbar[i] = 0;
}

// L2-direct sentinel fill for the probe h buffer (st.cg)
__global__ void k_fillp() {
    int idx = blockIdx.x * 256 + threadIdx.x;      // 131072 uint4
    __stcg((uint4*)g_Hp + idx, make_uint4(SENT, SENT, SENT, SENT));
}

__global__ void k_sums(const float* __restrict__ x) {
    int row  = blockIdx.x * 8 + (threadIdx.x >> 5);
    int lane = threadIdx.x & 31;
    const float4* xr = (const float4*)(x + (size_t)row * TWOK);
    float s = 0.f;
#pragma unroll
    for (int i = 0; i < 4; i++) {
        float4 v = xr[i * 32 + lane];
        s += v.x + v.y + v.z + v.w;
    }
#pragma unroll
    for (int o = 16; o; o >>= 1) s += __shfl_xor_sync(0xffffffffu, s, o);
    if (!lane) g_s[row] = s;
}

__global__ void k_delta(const float* __restrict__ delta,
                        const float* __restrict__ Wd,
                        const float* __restrict__ bd) {
    int i = blockIdx.x * 256 + threadIdx.x;
    float ed = expf(-(delta[i] * Wd[0] + bd[0]));
    float* xr = g_xc + (size_t)i * KXC;
    xr[256] = ed;
#pragma unroll
    for (int j = 257; j < KXC; j++) xr[j] = 0.f;
}

// ----- count scan: ONE serial pass + parallel apply -----
__global__ void k_scanA(const float* __restrict__ x) {
    int idx = blockIdx.x * 256 + threadIdx.x;
    int f = idx & 511, seg = (idx >> 9) & 7, b = idx >> 12;
    const float* sp = g_s + b * Tn + seg * 128;
    const float* xp = x    + ((size_t)b * Tn + seg * 128) * TWOK + f;
    float*       cp = g_cl + ((size_t)b * Tn + seg * 128) * TWOK + f;
    float c = 0.f;
#pragma unroll 4
    for (int tt = 0; tt < 128; tt++) {
        c = fmaf(sp[tt], c, xp[(size_t)tt * TWOK]);
        cp[(size_t)tt * TWOK] = c;
    }
}
__global__ void k_Pt() {
    int idx = blockIdx.x * 256 + threadIdx.x;
    if (idx >= Bn * 8) return;
    int b = idx >> 3, seg = idx & 7;
    const float* sp = g_s + b * Tn + seg * 128;
    float* pp = g_Pt + b * Tn + seg * 128;
    float p = 1.f;
    for (int tt = 0; tt < 128; tt++) { p *= sp[tt]; pp[tt] = p; }
}
__global__ void k_carry() {
    int idx = blockIdx.x * 256 + threadIdx.x;
    int b = idx >> 9, f = idx & 511;
    float c = 0.f;
#pragma unroll
    for (int j = 0; j < 8; j++) {
        g_Cin[(b * 8 + j) * 512 + f] = c;
        float P = g_Pt[b * Tn + j * 128 + 127];
        float Qe = g_cl[((size_t)b * Tn + j * 128 + 127) * TWOK + f];
        c = fmaf(P, c, Qe);
    }
}
__global__ void k_apply() {
    int gid = blockIdx.x * 256 + threadIdx.x;
    int row = gid >> 7, f4 = gid & 127;
    int b = row >> 10, t = row & 1023, seg = t >> 7;
    float A = g_Pt[row];
    float4* qp = (float4*)&g_cl[(size_t)row * TWOK + f4 * 4];
    float4 qv = *qp;
    float4 ci = *(const float4*)&g_Cin[((b << 3) + seg) * 512 + f4 * 4];
    qv.x = log1pf(fmaf(ci.x, A, qv.x));
    qv.y = log1pf(fmaf(ci.y, A, qv.y));
    qv.z = log1pf(fmaf(ci.z, A, qv.z));
    qv.w = log1pf(fmaf(ci.w, A, qv.w));
    *qp = qv;
}

__global__ void k_wlp(const float* __restrict__ Wl, const float* __restrict__ bl) {
    int i = blockIdx.x * 256 + threadIdx.x;
    if (i >= KXC * FH) return;
    int k = i / FH, jp = i % FH;
    int orig = (jp & 3) * 256 + (jp >> 2);
    g_WlP[i] = (k < 2 * En + 1) ? Wl[k * FH + orig] : 0.f;
    if (k == 0) g_blP[jp] = bl[orig];
}

// ---------------- fp32x2 SGEMM ----------------
template <int EPI>
__global__ void __launch_bounds__(256, 1) sgemm(
    const float* __restrict__ A, int lda,
    const float* __restrict__ Bm, int ldb,
    float* __restrict__ C, int ldc, int coff,
    const float* __restrict__ bias,
    const float* __restrict__ q,
    int K) {
    __shared__ __align__(16) float2 As2[2][4][128];
    __shared__ __align__(16) float2 Bs2[2][4][128];
    const int row0 = blockIdx.x * 128, col0 = blockIdx.y * 128;
    const int tid = threadIdx.x;
    const int ar = tid >> 1, aq = tid & 1;
    const int w = tid >> 5, lane = tid & 31;
    const int bk2 = w >> 1, bc = (w & 1) * 64 + lane * 2;
    const int ty = tid >> 4, tx = tid & 15;

    const float* Ap  = A + (size_t)(row0 + ar) * lda + aq * 4;
    const float* Bp0 = Bm + col0 + bc;

    unsigned long long acc[8][8];
#pragma unroll
    for (int i = 0; i < 8; i++)
#pragma unroll
        for (int j = 0; j < 8; j++) acc[i][j] = 0ull;

    {
        float4 av = *(const float4*)Ap;
        float2 b0 = *(const float2*)(Bp0 + (size_t)(2 * bk2) * ldb);
        float2 b1 = *(const float2*)(Bp0 + (size_t)(2 * bk2 + 1) * ldb);
        As2[0][2 * aq][ar]     = make_float2(av.x, av.y);
        As2[0][2 * aq + 1][ar] = make_float2(av.z, av.w);
        *(float4*)&Bs2[0][bk2][bc] = make_float4(b0.x, b1.x, b0.y, b1.y);
    }
    __syncthreads();

    int buf = 0;
    for (int k0 = 0; k0 < K; k0 += 8) {
        const bool more = (k0 + 8 < K);
        float4 avn; float2 b0n, b1n;
        if (more) {
            avn = *(const float4*)(Ap + k0 + 8);
            b0n = *(const float2*)(Bp0 + (size_t)(k0 + 8 + 2 * bk2) * ldb);
            b1n = *(const float2*)(Bp0 + (size_t)(k0 + 8 + 2 * bk2 + 1) * ldb);
        }
#pragma unroll
        for (int kk2 = 0; kk2 < 4; kk2++) {
            ulonglong2 a01 = *(const ulonglong2*)&As2[buf][kk2][ty * 8];
            ulonglong2 a23 = *(const ulonglong2*)&As2[buf][kk2][ty * 8 + 2];
            ulonglong2 a45 = *(const ulonglong2*)&As2[buf][kk2][ty * 8 + 4];
            ulonglong2 a67 = *(const ulonglong2*)&As2[buf][kk2][ty * 8 + 6];
            ulonglong2 b01 = *(const ulonglong2*)&Bs2[buf][kk2][tx * 8];
            ulonglong2 b23 = *(const ulonglong2*)&Bs2[buf][kk2][tx * 8 + 2];
            ulonglong2 b45 = *(const ulonglong2*)&Bs2[buf][kk2][tx * 8 + 4];
            ulonglong2 b67 = *(const ulonglong2*)&Bs2[buf][kk2][tx * 8 + 6];
            unsigned long long aa[8] = {a01.x, a01.y, a23.x, a23.y,
                                        a45.x, a45.y, a67.x, a67.y};
            unsigned long long bb[8] = {b01.x, b01.y, b23.x, b23.y,
                                        b45.x, b45.y, b67.x, b67.y};
#pragma unroll
            for (int i = 0; i < 8; i++)
#pragma unroll
                for (int j = 0; j < 8; j++) fma2(acc[i][j], aa[i], bb[j]);
        }
        if (more) {
            As2[buf ^ 1][2 * aq][ar]     = make_float2(avn.x, avn.y);
            As2[buf ^ 1][2 * aq + 1][ar] = make_float2(avn.z, avn.w);
            *(float4*)&Bs2[buf ^ 1][bk2][bc] = make_float4(b0n.x, b1n.x, b0n.y, b1n.y);
        }
        __syncthreads();
        buf ^= 1;
    }

#pragma unroll
    for (int i = 0; i < 8; i++) {
        size_t r = (size_t)row0 + ty * 8 + i;
        size_t rout = r;
        if (EPI == 2) rout = ((r & 1023) << 6) + (r >> 10);
#pragma unroll
        for (int j = 0; j < 8; j++) {
            int c = col0 + tx * 8 + j;
            float2 p = unpk(acc[i][j]);
            float v = p.x + p.y + bias[c];
            if (EPI == 1) {
                size_t qr = ((size_t)(r & 63) << 10) + (r >> 6);
                v = q[qr * 256 + c] * sigf(v);
            }
            C[rout * ldc + coff + c] = v;
        }
    }
}

// ---------------- persistent LSTM scan: 2-col/lane layout + R9 barrier ----------------
// Grid 128 = 8 batch-groups (i) x 16 col-groups (j).
// CTA (i,j): batches [8i,8i+8), permuted cols [64j,64j+64).
// Warp w: cols 64j+8w..+8; lane = (c2=lane>>3 in [0,4), kc=lane&7 in [0,8)).
// Lane owns 2 cols x 32 k of Ul in regs; per batch-dot 8 LDS.128 (shared by both cols).
// h chunks skewed at 36-float stride (kc*144B -> conflict-free).
__global__ void __launch_bounds__(256, 1) k_lstm(
    const float* __restrict__ Ul,
    const float* __restrict__ pre,
    float* __restrict__ Hbuf,
    int* __restrict__ rbar) {
    __shared__ __align__(16) float hs[8 * HROW];
    __shared__ __align__(16) float zs[8 * 64];

    const int i  = blockIdx.x >> 4, j = blockIdx.x & 15;
    const int tid = threadIdx.x;
    const int w = tid >> 5, lane = tid & 31;
    const int c2 = lane >> 3, kc = lane & 7;
    const int k0 = kc * 32;
    const int pc0 = 64 * j + 8 * w + 2 * c2;
    const int pc1 = pc0 + 1;
    const int orig0 = (pc0 & 3) * 256 + (pc0 >> 2);
    const int orig1 = (pc1 & 3) * 256 + (pc1 >> 2);

    // Ul chunks in registers: 2 cols x 32 k = 2 x 16 packed pairs
    unsigned long long ureg0[16], ureg1[16];
#pragma unroll
    for (int m = 0; m < 16; m++) {
        float u0 = Ul[(size_t)(k0 + 2 * m) * FH + orig0];
        float u1 = Ul[(size_t)(k0 + 2 * m + 1) * FH + orig0];
        asm("mov.b64 %0, {%1, %2};" : "=l"(ureg0[m]) : "f"(u0), "f"(u1));
        float v0 = Ul[(size_t)(k0 + 2 * m) * FH + orig1];
        float v1 = Ul[(size_t)(k0 + 2 * m + 1) * FH + orig1];
        asm("mov.b64 %0, {%1, %2};" : "=l"(ureg1[m]) : "f"(v0), "f"(v1));
    }

    const int b_l = lane & 7, u_l = lane >> 3;           // gate mapping (lane<16)
    float cst = 0.f;
    int* bar = rbar + i * 32;
    const int pcolz = pc0 + kc;                          // valid for kc<2

    float prer[8], pren[8];
    if (kc < 2) {
#pragma unroll
        for (int bi = 0; bi < 8; bi++)
            prer[bi] = pre[(size_t)(8 * i + bi) * FH + pcolz];
    }

    for (int t = 0; t < Tn; t++) {
        // ---- stage 8 batch h-rows into skewed smem (36-float chunks) ----
        if (t == 0) {
#pragma unroll
            for (int e = 0; e < 2; e++) {
                int qi = tid * 2 + e;
                int b = qi >> 6, k4 = qi & 63;
                *(float4*)&hs[b * HROW + (k4 >> 3) * 36 + (k4 & 7) * 4] =
                    make_float4(0.f, 0.f, 0.f, 0.f);
            }
        } else {
            const float* src = Hbuf + ((size_t)(t - 1) * Bn + 8 * i) * Hh;
#pragma unroll
            for (int e = 0; e < 2; e++) {
                int qi = tid * 2 + e;
                int b = qi >> 6, k4 = qi & 63;
                float4 v = __ldcg((const float4*)(src + b * Hh + k4 * 4));
                *(float4*)&hs[b * HROW + (k4 >> 3) * 36 + (k4 & 7) * 4] = v;
            }
        }
        if (kc < 2 && t + 1 < Tn) {
#pragma unroll
            for (int bi = 0; bi < 8; bi++)
                pren[bi] = __ldcg(pre + ((size_t)(t + 1) * Bn + 8 * i + bi) * FH + pcolz);
        }
        __syncthreads();

        // ---- z-partials: 2 cols per lane, 32-k chunk, 8 LDS.128/bi ----
#pragma unroll
        for (int bi = 0; bi < 8; bi++) {
            const ulonglong2* hrow = (const ulonglong2*)&hs[bi * HROW + kc * 36];
            unsigned long long a00 = 0ull, a01 = 0ull, a10 = 0ull, a11 = 0ull;
#pragma unroll
            for (int m = 0; m < 8; m++) {
                ulonglong2 hv = hrow[m];
                fma2(a00, ureg0[2 * m],     hv.x);
                fma2(a01, ureg0[2 * m + 1], hv.y);
                fma2(a10, ureg1[2 * m],     hv.x);
                fma2(a11, ureg1[2 * m + 1], hv.y);
            }
            float2 p00 = unpk(a00), p01 = unpk(a01);
            float2 p10 = unpk(a10), p11 = unpk(a11);
            float v0 = (p00.x + p00.y) + (p01.x + p01.y);
            float v1 = (p10.x + p10.y) + (p11.x + p11.y);
            v0 += __shfl_xor_sync(0xffffffffu, v0, 1);
            v1 += __shfl_xor_sync(0xffffffffu, v1, 1);
            v0 += __shfl_xor_sync(0xffffffffu, v0, 2);
            v1 += __shfl_xor_sync(0xffffffffu, v1, 2);
            v0 += __shfl_xor_sync(0xffffffffu, v0, 4);
            v1 += __shfl_xor_sync(0xffffffffu, v1, 4);
            if (kc < 2)
                zs[w * 64 + bi * 8 + 2 * c2 + kc] = ((kc == 0) ? v0 : v1) + prer[bi];
        }
        if (kc < 2) {
#pragma unroll
            for (int bi = 0; bi < 8; bi++) prer[bi] = pren[bi];
        }
        __syncwarp();

        // ---- gates in-warp (lane<16), MUFU tanh ----
        if (lane < 16) {
            float4 z4 = *(const float4*)&zs[w * 64 + b_l * 8 + u_l * 4];
            float ig = sigf(z4.x);
            float fg = sigf(z4.y);
            float gg = __tanhf(z4.z);
            float og = sigf(z4.w);
            cst = fg * cst + ig * gg;
            float h = og * __tanhf(cst);
            __stcg(&Hbuf[((size_t)t * Bn + 8 * i + b_l) * Hh + 16 * j + 2 * w + u_l], h);
        }
        __syncthreads();

        // ---- per-row barrier: 16 CTA-granular arrivals (R9 known-good) ----
        if (tid == 0) {
            asm volatile("red.release.gpu.global.add.s32 [%0], 1;"
                         :: "l"(bar) : "memory");
            int target = 16 * (t + 1), v;
            do {
                asm volatile("ld.relaxed.gpu.global.b32 %0, [%1];"
                             : "=r"(v) : "l"(bar) : "memory");
            } while (v < target);
            asm volatile("ld.acquire.gpu.global.b32 %0, [%1];"
                         : "=r"(v) : "l"(bar) : "memory");
        }
        __syncthreads();
    }
}

// ---------------- PROBE ONLY: sentinel dataflow + 2-col layout ----------------
__global__ void __launch_bounds__(256, 1) k_lstm_sent(
    const float* __restrict__ Ul,
    const float* __restrict__ pre,
    float* __restrict__ Hbuf) {
    __shared__ __align__(16) float hs[8 * HROW];
    __shared__ __align__(16) float zs[8 * 64];

    const int i  = blockIdx.x >> 4, j = blockIdx.x & 15;
    const int tid = threadIdx.x;
    const int w = tid >> 5, lane = tid & 31;
    const int c2 = lane >> 3, kc = lane & 7;
    const int k0 = kc * 32;
    const int pc0 = 64 * j + 8 * w + 2 * c2;
    const int pc1 = pc0 + 1;
    const int orig0 = (pc0 & 3) * 256 + (pc0 >> 2);
    const int orig1 = (pc1 & 3) * 256 + (pc1 >> 2);

    unsigned long long ureg0[16], ureg1[16];
#pragma unroll
    for (int m = 0; m < 16; m++) {
        float u0 = Ul[(size_t)(k0 + 2 * m) * FH + orig0];
        float u1 = Ul[(size_t)(k0 + 2 * m + 1) * FH + orig0];
        asm("mov.b64 %0, {%1, %2};" : "=l"(ureg0[m]) : "f"(u0), "f"(u1));
        float v0 = Ul[(size_t)(k0 + 2 * m) * FH + orig1];
        float v1 = Ul[(size_t)(k0 + 2 * m + 1) * FH + orig1];
        asm("mov.b64 %0, {%1, %2};" : "=l"(ureg1[m]) : "f"(v0), "f"(v1));
    }

    const int b_l = lane & 7, u_l = lane >> 3;
    float cst = 0.f;
    const int pcolz = pc0 + kc;

    const int qi0 = tid * 2, qi1 = tid * 2 + 1;
    const int sb0 = qi0 >> 6, k40 = qi0 & 63;
    const int sb1 = qi1 >> 6, k41 = qi1 & 63;
    float* d0 = &hs[sb0 * HROW + (k40 >> 3) * 36 + (k40 & 7) * 4];
    float* d1 = &hs[sb1 * HROW + (k41 >> 3) * 36 + (k41 & 7) * 4];

    float prer[8], pren[8];
    if (kc < 2) {
#pragma unroll
        for (int bi = 0; bi < 8; bi++)
            prer[bi] = pre[(size_t)(8 * i + bi) * FH + pcolz];
    }

    for (int t = 0; t < PROBE_T; t++) {
        if (kc < 2 && t + 1 < PROBE_T) {
#pragma unroll
            for (int bi = 0; bi < 8; bi++)
                pren[bi] = __ldcg(pre + ((size_t)(t + 1) * Bn + 8 * i + bi) * FH + pcolz);
        }
        if (t == 0) {
            *(float4*)d0 = make_float4(0.f, 0.f, 0.f, 0.f);
            *(float4*)d1 = make_float4(0.f, 0.f, 0.f, 0.f);
        } else {
            const float* src = Hbuf + ((size_t)(t - 1) * Bn + 8 * i) * Hh;
            const float4* p0 = (const float4*)(src + sb0 * Hh + k40 * 4);
            const float4* p1 = (const float4*)(src + sb1 * Hh + k41 * 4);
            float4 v0, v1;
            for (;;) {
                v0 = ldcg4v(p0);
                v1 = ldcg4v(p1);
                unsigned bad =
                    (__float_as_uint(v0.x) == SENT) | (__float_as_uint(v0.y) == SENT) |
                    (__float_as_uint(v0.z) == SENT) | (__float_as_uint(v0.w) == SENT) |
                    (__float_as_uint(v1.x) == SENT) | (__float_as_uint(v1.y) == SENT) |
                    (__float_as_uint(v1.z) == SENT) | (__float_as_uint(v1.w) == SENT);
                if (!bad) break;
            }
            *(float4*)d0 = v0;
            *(float4*)d1 = v1;
        }
        __syncthreads();

#pragma unroll
        for (int bi = 0; bi < 8; bi++) {
            const ulonglong2* hrow = (const ulonglong2*)&hs[bi * HROW + kc * 36];
            unsigned long long a00 = 0ull, a01 = 0ull, a10 = 0ull, a11 = 0ull;
#pragma unroll
            for (int m = 0; m < 8; m++) {
                ulonglong2 hv = hrow[m];
                fma2(a00, ureg0[2 * m],     hv.x);
                fma2(a01, ureg0[2 * m + 1], hv.y);
                fma2(a10, ureg1[2 * m],     hv.x);
                fma2(a11, ureg1[2 * m + 1], hv.y);
            }
            float2 p00 = unpk(a00), p01 = unpk(a01);
            float2 p10 = unpk(a10), p11 = unpk(a11);
            float v0 = (p00.x + p00.y) + (p01.x + p01.y);
            float v1 = (p10.x + p10.y) + (p11.x + p11.y);
            v0 += __shfl_xor_sync(0xffffffffu, v0, 1);
            v1 += __shfl_xor_sync(0xffffffffu, v1, 1);
            v0 += __shfl_xor_sync(0xffffffffu, v0, 2);
            v1 += __shfl_xor_sync(0xffffffffu, v1, 2);
            v0 += __shfl_xor_sync(0xffffffffu, v0, 4);
            v1 += __shfl_xor_sync(0xffffffffu, v1, 4);
            if (kc < 2)
                zs[w * 64 + bi * 8 + 2 * c2 + kc] = ((kc == 0) ? v0 : v1) + prer[bi];
        }
        if (kc < 2) {
#pragma unroll
            for (int bi = 0; bi < 8; bi++) prer[bi] = pren[bi];
        }
        __syncwarp();

        if (lane < 16) {
            float4 z4 = *(const float4*)&zs[w * 64 + b_l * 8 + u_l * 4];
            float ig = sigf(z4.x);
            float fg = sigf(z4.y);
            float gg = __tanhf(z4.z);
            float og = sigf(z4.w);
            cst = fg * cst + ig * gg;
            float h = og * __tanhf(cst);
            __stcg(&Hbuf[((size_t)t * Bn + 8 * i + b_l) * Hh + 16 * j + 2 * w + u_l], h);
        }
        __syncthreads();
    }
}

// rows of g_Y are in t*64+b order; out is [b][t]
__global__ void k_rowsum(float* __restrict__ out) {
    int row  = blockIdx.x * 8 + (threadIdx.x >> 5);
    int lane = threadIdx.x & 31;
    const float4* yr = (const float4*)(g_Y + (size_t)row * Hh);
    float4 a = yr[lane], b = yr[lane + 32];
    float s = a.x + a.y + a.z + a.w + b.x + b.y + b.z + b.w;
#pragma unroll
    for (int o = 16; o; o >>= 1) s += __shfl_xor_sync(0xffffffffu, s, o);
    if (!lane) out[(row & 63) * Tn + (row >> 6)] = s;
}

// ---------------- launch ----------------
extern "C" void kernel_launch(void* const* d_in, const int* in_sizes, int n_in,
                              void* d_out, int out_size) {
    const float* x     = (const float*)d_in[0];
    const float* delta = (const float*)d_in[1];
    const float* q     = (const float*)d_in[2];
    const float* Wx    = (const float*)d_in[3];
    const float* bx    = (const float*)d_in[4];
    const float* Wc    = (const float*)d_in[5];
    const float* bc    = (const float*)d_in[6];
    const float* Wd    = (const float*)d_in[7];
    const float* bd    = (const float*)d_in[8];
    const float* Wl    = (const float*)d_in[9];
    const float* Ul    = (const float*)d_in[10];
    const float* bl    = (const float*)d_in[11];
    const float* Wo    = (const float*)d_in[12];
    const float* bo    = (const float*)d_in[13];
    float* out = (float*)d_out;

    float *p_xc, *p_cl, *p_pre, *p_H, *p_Hp, *p_Y, *p_WlP, *p_blP;
    int *p_bar;
    cudaGetSymbolAddress((void**)&p_xc,  g_xc);
    cudaGetSymbolAddress((void**)&p_cl,  g_cl);
    cudaGetSymbolAddress((void**)&p_pre, g_pre);
    cudaGetSymbolAddress((void**)&p_H,   g_H);
    cudaGetSymbolAddress((void**)&p_Hp,  g_Hp);
    cudaGetSymbolAddress((void**)&p_Y,   g_Y);
    cudaGetSymbolAddress((void**)&p_WlP, g_WlP);
    cudaGetSymbolAddress((void**)&p_blP, g_blP);
    cudaGetSymbolAddress((void**)&p_bar, g_rbar);

    k_reset<<<1, 256>>>();                                 // #1
    k_sums<<<BT / 8, 256>>>(x);                            // #2
    k_fillp<<<PROBE_T * Bn * Hh / 1024, 256>>>();          // #3
    // #4: sentinel + 2-col probe in the ncu slot (g_Hp scratch only)
    k_lstm_sent<<<128, 256>>>(Ul, p_pre, p_Hp);
    k_delta<<<BT / 256, 256>>>(delta, Wd, bd);             // #5
    k_wlp<<<(KXC * FH + 255) / 256, 256>>>(Wl, bl);        // #6

    // count scan: one serial pass + parallel apply
    k_scanA<<<1024, 256>>>(x);
    k_Pt<<<2, 256>>>();
    k_carry<<<128, 256>>>();
    k_apply<<<BT * 128 / 256, 256>>>();

    // embed_x -> xc[:, 0:128]
    sgemm<0><<<dim3(BT / 128, 1), 256>>>(x, TWOK, Wx, En, p_xc, KXC, 0, bx, nullptr, TWOK);
    // embed_count -> xc[:, 128:256]
    sgemm<0><<<dim3(BT / 128, 1), 256>>>(p_cl, TWOK, Wc, En, p_xc, KXC, 128, bc, nullptr, TWOK);
    // pre = xc @ WlP + blP, stored row-remapped to [t*64+b][FH]
    sgemm<2><<<dim3(BT / 128, FH / 128), 256>>>(p_xc, KXC, p_WlP, FH, p_pre, FH, 0, p_blP, nullptr, KXC);

    // sequential LSTM scan (2-col layout, R9 barrier)
    k_lstm<<<128, 256>>>(Ul, p_pre, p_H, p_bar);

    // Y = sigmoid(H @ Wo + bo) * q   (rows in t*64+b order)
    sgemm<1><<<dim3(BT / 128, Hh / 128), 256>>>(p_H, Hh, Wo, Hh, p_Y, Hh, 0, bo, q, Hh);
    // out = rowsum(Y) with row remap
    k_rowsum<<<BT / 8, 256>>>(out);
}

// round 13
// speedup vs baseline: 1.0333x; 1.0333x over previous
#include <cuda_runtime.h>
#include <cstdint>
#include <math.h>

// Problem dims
#define Bn   64
#define Tn   1024
#define TWOK 512
#define En   128
#define Hh   256
#define FH   1024          // 4*H
#define BT   (Bn*Tn)       // 65536
#define KXC  264           // 2E+1 padded to multiple of 8
#define HROW 288           // skewed h row stride (4 chunks of 72 floats)

// ---------------- packed fp32x2 helpers ----------------
__device__ __forceinline__ void fma2(unsigned long long& acc,
                                     unsigned long long a,
                                     unsigned long long b) {
    asm("fma.rn.f32x2 %0, %1, %2, %0;" : "+l"(acc) : "l"(a), "l"(b));
}
__device__ __forceinline__ float2 unpk(unsigned long long v) {
    float2 r;
    asm("mov.b64 {%0, %1}, %2;" : "=f"(r.x), "=f"(r.y) : "l"(v));
    return r;
}
__device__ __forceinline__ float sigf(float x) {
    return fmaf(__tanhf(0.5f * x), 0.5f, 0.5f);
}

// ---------------- scratch (static device globals) ----------------
__device__ float g_s[BT];
__device__ float g_Pt[BT];
__device__ float g_Cin[Bn * 8 * TWOK];
__device__ float g_cl[(size_t)BT * TWOK];
__device__ float g_xc[(size_t)BT * KXC];
__device__ float g_WlP[KXC * FH];
__device__ float g_blP[FH];
__device__ float g_pre[(size_t)BT * FH];           // [t*64+b][FH] permuted cols
__device__ float g_H[(size_t)BT * Hh];             // [t][b][256] time-major
__device__ float g_Y[(size_t)BT * Hh];             // rows in t*64+b order
__device__ int   g_rbar[8 * 32];                   // row barriers (128B apart)

// ---------------- tiny kernels ----------------
__global__ void k_reset() {
    int i = threadIdx.x;
    if (i < 8 * 32) g_rbar[i] = 0;
}

__global__ void k_sums(const float* __restrict__ x) {
    int row  = blockIdx.x * 8 + (threadIdx.x >> 5);
    int lane = threadIdx.x & 31;
    const float4* xr = (const float4*)(x + (size_t)row * TWOK);
    float s = 0.f;
#pragma unroll
    for (int i = 0; i < 4; i++) {
        float4 v = xr[i * 32 + lane];
        s += v.x + v.y + v.z + v.w;
    }
#pragma unroll
    for (int o = 16; o; o >>= 1) s += __shfl_xor_sync(0xffffffffu, s, o);
    if (!lane) g_s[row] = s;
}

__global__ void k_delta(const float* __restrict__ delta,
                        const float* __restrict__ Wd,
                        const float* __restrict__ bd) {
    int i = blockIdx.x * 256 + threadIdx.x;
    float ed = expf(-(delta[i] * Wd[0] + bd[0]));
    float* xr = g_xc + (size_t)i * KXC;
    xr[256] = ed;
#pragma unroll
    for (int j = 257; j < KXC; j++) xr[j] = 0.f;
}

// ----- count scan: ONE serial pass + parallel apply -----
__global__ void k_scanA(const float* __restrict__ x) {
    int idx = blockIdx.x * 256 + threadIdx.x;
    int f = idx & 511, seg = (idx >> 9) & 7, b = idx >> 12;
    const float* sp = g_s + b * Tn + seg * 128;
    const float* xp = x    + ((size_t)b * Tn + seg * 128) * TWOK + f;
    float*       cp = g_cl + ((size_t)b * Tn + seg * 128) * TWOK + f;
    float c = 0.f;
#pragma unroll 4
    for (int tt = 0; tt < 128; tt++) {
        c = fmaf(sp[tt], c, xp[(size_t)tt * TWOK]);
        cp[(size_t)tt * TWOK] = c;
    }
}
__global__ void k_Pt() {
    int idx = blockIdx.x * 256 + threadIdx.x;
    if (idx >= Bn * 8) return;
    int b = idx >> 3, seg = idx & 7;
    const float* sp = g_s + b * Tn + seg * 128;
    float* pp = g_Pt + b * Tn + seg * 128;
    float p = 1.f;
    for (int tt = 0; tt < 128; tt++) { p *= sp[tt]; pp[tt] = p; }
}
__global__ void k_carry() {
    int idx = blockIdx.x * 256 + threadIdx.x;
    int b = idx >> 9, f = idx & 511;
    float c = 0.f;
#pragma unroll
    for (int j = 0; j < 8; j++) {
        g_Cin[(b * 8 + j) * 512 + f] = c;
        float P = g_Pt[b * Tn + j * 128 + 127];
        float Qe = g_cl[((size_t)b * Tn + j * 128 + 127) * TWOK + f];
        c = fmaf(P, c, Qe);
    }
}
__global__ void k_apply() {
    int gid = blockIdx.x * 256 + threadIdx.x;
    int row = gid >> 7, f4 = gid & 127;
    int b = row >> 10, t = row & 1023, seg = t >> 7;
    float A = g_Pt[row];
    float4* qp = (float4*)&g_cl[(size_t)row * TWOK + f4 * 4];
    float4 qv = *qp;
    float4 ci = *(const float4*)&g_Cin[((b << 3) + seg) * 512 + f4 * 4];
    qv.x = log1pf(fmaf(ci.x, A, qv.x));
    qv.y = log1pf(fmaf(ci.y, A, qv.y));
    qv.z = log1pf(fmaf(ci.z, A, qv.z));
    qv.w = log1pf(fmaf(ci.w, A, qv.w));
    *qp = qv;
}

__global__ void k_wlp(const float* __restrict__ Wl, const float* __restrict__ bl) {
    int i = blockIdx.x * 256 + threadIdx.x;
    if (i >= KXC * FH) return;
    int k = i / FH, jp = i % FH;
    int orig = (jp & 3) * 256 + (jp >> 2);
    g_WlP[i] = (k < 2 * En + 1) ? Wl[k * FH + orig] : 0.f;
    if (k == 0) g_blP[jp] = bl[orig];
}

// ---------------- fp32x2 SGEMM ----------------
// EPI 0: plain.  EPI 1: sigmoid*q (rows t*64+b).  EPI 2: row remap b*Tn+t -> t*64+b.
template <int EPI>
__global__ void __launch_bounds__(256, 1) sgemm(
    const float* __restrict__ A, int lda,
    const float* __restrict__ Bm, int ldb,
    float* __restrict__ C, int ldc, int coff,
    const float* __restrict__ bias,
    const float* __restrict__ q,
    int K) {
    __shared__ __align__(16) float2 As2[2][4][128];
    __shared__ __align__(16) float2 Bs2[2][4][128];
    const int row0 = blockIdx.x * 128, col0 = blockIdx.y * 128;
    const int tid = threadIdx.x;
    const int ar = tid >> 1, aq = tid & 1;
    const int w = tid >> 5, lane = tid & 31;
    const int bk2 = w >> 1, bc = (w & 1) * 64 + lane * 2;
    const int ty = tid >> 4, tx = tid & 15;

    const float* Ap  = A + (size_t)(row0 + ar) * lda + aq * 4;
    const float* Bp0 = Bm + col0 + bc;

    unsigned long long acc[8][8];
#pragma unroll
    for (int i = 0; i < 8; i++)
#pragma unroll
        for (int j = 0; j < 8; j++) acc[i][j] = 0ull;

    {
        float4 av = *(const float4*)Ap;
        float2 b0 = *(const float2*)(Bp0 + (size_t)(2 * bk2) * ldb);
        float2 b1 = *(const float2*)(Bp0 + (size_t)(2 * bk2 + 1) * ldb);
        As2[0][2 * aq][ar]     = make_float2(av.x, av.y);
        As2[0][2 * aq + 1][ar] = make_float2(av.z, av.w);
        *(float4*)&Bs2[0][bk2][bc] = make_float4(b0.x, b1.x, b0.y, b1.y);
    }
    __syncthreads();

    int buf = 0;
    for (int k0 = 0; k0 < K; k0 += 8) {
        const bool more = (k0 + 8 < K);
        float4 avn; float2 b0n, b1n;
        if (more) {
            avn = *(const float4*)(Ap + k0 + 8);
            b0n = *(const float2*)(Bp0 + (size_t)(k0 + 8 + 2 * bk2) * ldb);
            b1n = *(const float2*)(Bp0 + (size_t)(k0 + 8 + 2 * bk2 + 1) * ldb);
        }
#pragma unroll
        for (int kk2 = 0; kk2 < 4; kk2++) {
            ulonglong2 a01 = *(const ulonglong2*)&As2[buf][kk2][ty * 8];
            ulonglong2 a23 = *(const ulonglong2*)&As2[buf][kk2][ty * 8 + 2];
            ulonglong2 a45 = *(const ulonglong2*)&As2[buf][kk2][ty * 8 + 4];
            ulonglong2 a67 = *(const ulonglong2*)&As2[buf][kk2][ty * 8 + 6];
            ulonglong2 b01 = *(const ulonglong2*)&Bs2[buf][kk2][tx * 8];
            ulonglong2 b23 = *(const ulonglong2*)&Bs2[buf][kk2][tx * 8 + 2];
            ulonglong2 b45 = *(const ulonglong2*)&Bs2[buf][kk2][tx * 8 + 4];
            ulonglong2 b67 = *(const ulonglong2*)&Bs2[buf][kk2][tx * 8 + 6];
            unsigned long long aa[8] = {a01.x, a01.y, a23.x, a23.y,
                                        a45.x, a45.y, a67.x, a67.y};
            unsigned long long bb[8] = {b01.x, b01.y, b23.x, b23.y,
                                        b45.x, b45.y, b67.x, b67.y};
#pragma unroll
            for (int i = 0; i < 8; i++)
#pragma unroll
                for (int j = 0; j < 8; j++) fma2(acc[i][j], aa[i], bb[j]);
        }
        if (more) {
            As2[buf ^ 1][2 * aq][ar]     = make_float2(avn.x, avn.y);
            As2[buf ^ 1][2 * aq + 1][ar] = make_float2(avn.z, avn.w);
            *(float4*)&Bs2[buf ^ 1][bk2][bc] = make_float4(b0n.x, b1n.x, b0n.y, b1n.y);
        }
        __syncthreads();
        buf ^= 1;
    }

#pragma unroll
    for (int i = 0; i < 8; i++) {
        size_t r = (size_t)row0 + ty * 8 + i;
        size_t rout = r;
        if (EPI == 2) rout = ((r & 1023) << 6) + (r >> 10);   // b*Tn+t -> t*64+b
#pragma unroll
        for (int j = 0; j < 8; j++) {
            int c = col0 + tx * 8 + j;
            float2 p = unpk(acc[i][j]);
            float v = p.x + p.y + bias[c];
            if (EPI == 1) {
                size_t qr = ((size_t)(r & 63) << 10) + (r >> 6);
                v = q[qr * 256 + c] * sigf(v);
            }
            C[rout * ldc + coff + c] = v;
        }
    }
}

// ---------------- persistent LSTM scan: R11 known-good (1-col, R9 barrier) ----------------
// Grid 128 = 8 batch-groups (i) x 16 col-groups (j).
// CTA (i,j): batches [8i,8i+8), permuted cols [64j,64j+64) = units [16j,16j+16).
// Warp w: cols 64j+8w..+8; lane (c=lane&7, kc=lane>>3) holds Ul 64-k chunk in regs.
// Row barrier over 16 CTAs: red.release + relaxed spin + acquire (tid0, CTA-granular).
__global__ void __launch_bounds__(256, 1) k_lstm(
    const float* __restrict__ Ul,
    const float* __restrict__ pre,
    float* __restrict__ Hbuf,
    int* __restrict__ rbar) {
    __shared__ __align__(16) float hs[8 * HROW];
    __shared__ __align__(16) float zs[8 * 64];

    const int i  = blockIdx.x >> 4, j = blockIdx.x & 15;
    const int tid = threadIdx.x;
    const int w = tid >> 5, lane = tid & 31;
    const int c = lane & 7, kc = lane >> 3;
    const int k0 = kc * 64;
    const int pcol = 64 * j + 8 * w + c;
    const int orig = (pcol & 3) * 256 + (pcol >> 2);

    unsigned long long ureg[32];
#pragma unroll
    for (int m = 0; m < 32; m++) {
        float u0 = Ul[(size_t)(k0 + 2 * m) * FH + orig];
        float u1 = Ul[(size_t)(k0 + 2 * m + 1) * FH + orig];
        asm("mov.b64 %0, {%1, %2};" : "=l"(ureg[m]) : "f"(u0), "f"(u1));
    }

    const int b_l = lane & 7, u_l = lane >> 3;
    float cst = 0.f;
    int* bar = rbar + i * 32;

    float prer[8], pren[8];
    if (kc == 0) {
#pragma unroll
        for (int bi = 0; bi < 8; bi++)
            prer[bi] = pre[(size_t)(8 * i + bi) * FH + pcol];
    }

    for (int t = 0; t < Tn; t++) {
        if (t == 0) {
#pragma unroll
            for (int e = 0; e < 2; e++) {
                int qi = tid * 2 + e;
                int b = qi >> 6, k4 = qi & 63, col = 4 * k4;
                *(float4*)&hs[b * HROW + (col >> 6) * 72 + (col & 63)] =
                    make_float4(0.f, 0.f, 0.f, 0.f);
            }
        } else {
            const float* src = Hbuf + ((size_t)(t - 1) * Bn + 8 * i) * Hh;
#pragma unroll
            for (int e = 0; e < 2; e++) {
                int qi = tid * 2 + e;
                int b = qi >> 6, k4 = qi & 63, col = 4 * k4;
                float4 v = __ldcg((const float4*)(src + b * Hh + col));
                *(float4*)&hs[b * HROW + (col >> 6) * 72 + (col & 63)] = v;
            }
        }
        if (kc == 0 && t + 1 < Tn) {
#pragma unroll
            for (int bi = 0; bi < 8; bi++)
                pren[bi] = __ldcg(pre + ((size_t)(t + 1) * Bn + 8 * i + bi) * FH + pcol);
        }
        __syncthreads();

#pragma unroll
        for (int bi = 0; bi < 8; bi++) {
            const ulonglong2* hrow = (const ulonglong2*)&hs[bi * HROW + kc * 72];
            unsigned long long a0 = 0ull, a1 = 0ull;
#pragma unroll
            for (int m = 0; m < 16; m++) {
                ulonglong2 hv = hrow[m];
                fma2(a0, ureg[2 * m],     hv.x);
                fma2(a1, ureg[2 * m + 1], hv.y);
            }
            float2 p0 = unpk(a0), p1 = unpk(a1);
            float v = (p0.x + p0.y) + (p1.x + p1.y);
            v += __shfl_xor_sync(0xffffffffu, v, 8);
            v += __shfl_xor_sync(0xffffffffu, v, 16);
            if (kc == 0) zs[w * 64 + bi * 8 + c] = v + prer[bi];
        }
        if (kc == 0) {
#pragma unroll
            for (int bi = 0; bi < 8; bi++) prer[bi] = pren[bi];
        }
        __syncwarp();

        if (lane < 16) {
            float4 z4 = *(const float4*)&zs[w * 64 + b_l * 8 + u_l * 4];
            float ig = sigf(z4.x);
            float fg = sigf(z4.y);
            float gg = __tanhf(z4.z);
            float og = sigf(z4.w);
            cst = fg * cst + ig * gg;
            float h = og * __tanhf(cst);
            __stcg(&Hbuf[((size_t)t * Bn + 8 * i + b_l) * Hh + 16 * j + 2 * w + u_l], h);
        }
        __syncthreads();

        if (tid == 0) {
            asm volatile("red.release.gpu.global.add.s32 [%0], 1;"
                         :: "l"(bar) : "memory");
            int target = 16 * (t + 1), v;
            do {
                asm volatile("ld.relaxed.gpu.global.b32 %0, [%1];"
                             : "=r"(v) : "l"(bar) : "memory");
            } while (v < target);
            asm volatile("ld.acquire.gpu.global.b32 %0, [%1];"
                         : "=r"(v) : "l"(bar) : "memory");
        }
        __syncthreads();
    }
}

// rows of g_Y are in t*64+b order; out is [b][t]
__global__ void k_rowsum(float* __restrict__ out) {
    int row  = blockIdx.x * 8 + (threadIdx.x >> 5);
    int lane = threadIdx.x & 31;
    const float4* yr = (const float4*)(g_Y + (size_t)row * Hh);
    float4 a = yr[lane], b = yr[lane + 32];
    float s = a.x + a.y + a.z + a.w + b.x + b.y + b.z + b.w;
#pragma unroll
    for (int o = 16; o; o >>= 1) s += __shfl_xor_sync(0xffffffffu, s, o);
    if (!lane) out[(row & 63) * Tn + (row >> 6)] = s;
}

// ---------------- launch ----------------
extern "C" void kernel_launch(void* const* d_in, const int* in_sizes, int n_in,
                              void* d_out, int out_size) {
    const float* x     = (const float*)d_in[0];
    const float* delta = (const float*)d_in[1];
    const float* q     = (const float*)d_in[2];
    const float* Wx    = (const float*)d_in[3];
    const float* bx    = (const float*)d_in[4];
    const float* Wc    = (const float*)d_in[5];
    const float* bc    = (const float*)d_in[6];
    const float* Wd    = (const float*)d_in[7];
    const float* bd    = (const float*)d_in[8];
    const float* Wl    = (const float*)d_in[9];
    const float* Ul    = (const float*)d_in[10];
    const float* bl    = (const float*)d_in[11];
    const float* Wo    = (const float*)d_in[12];
    const float* bo    = (const float*)d_in[13];
    float* out = (float*)d_out;

    float *p_xc, *p_cl, *p_pre, *p_H, *p_Y, *p_WlP, *p_blP;
    int *p_bar;
    cudaGetSymbolAddress((void**)&p_xc,  g_xc);
    cudaGetSymbolAddress((void**)&p_cl,  g_cl);
    cudaGetSymbolAddress((void**)&p_pre, g_pre);
    cudaGetSymbolAddress((void**)&p_H,   g_H);
    cudaGetSymbolAddress((void**)&p_Y,   g_Y);
    cudaGetSymbolAddress((void**)&p_WlP, g_WlP);
    cudaGetSymbolAddress((void**)&p_blP, g_blP);
    cudaGetSymbolAddress((void**)&p_bar, g_rbar);

    k_reset<<<1, 256>>>();                                 // #1
    k_sums<<<BT / 8, 256>>>(x);                            // #2
    k_delta<<<BT / 256, 256>>>(delta, Wd, bd);             // #3
    // #4 (ncu slot): REAL embed_x GEMM — depends only on inputs, free profiling
    sgemm<0><<<dim3(BT / 128, 1), 256>>>(x, TWOK, Wx, En, p_xc, KXC, 0, bx, nullptr, TWOK);
    k_wlp<<<(KXC * FH + 255) / 256, 256>>>(Wl, bl);        // #5

    // count scan: one serial pass + parallel apply
    k_scanA<<<1024, 256>>>(x);
    k_Pt<<<2, 256>>>();
    k_carry<<<128, 256>>>();
    k_apply<<<BT * 128 / 256, 256>>>();

    // embed_count -> xc[:, 128:256]
    sgemm<0><<<dim3(BT / 128, 1), 256>>>(p_cl, TWOK, Wc, En, p_xc, KXC, 128, bc, nullptr, TWOK);
    // pre = xc @ WlP + blP, stored row-remapped to [t*64+b][FH]
    sgemm<2><<<dim3(BT / 128, FH / 128), 256>>>(p_xc, KXC, p_WlP, FH, p_pre, FH, 0, p_blP, nullptr, KXC);

    // sequential LSTM scan (R11 best config)
    k_lstm<<<128, 256>>>(Ul, p_pre, p_H, p_bar);

    // Y = sigmoid(H @ Wo + bo) * q   (rows in t*64+b order)
    sgemm<1><<<dim3(BT / 128, Hh / 128), 256>>>(p_H, Hh, Wo, Hh, p_Y, Hh, 0, bo, q, Hh);
    // out = rowsum(Y) with row remap
    k_rowsum<<<BT / 8, 256>>>(out);
}